// round 2
// baseline (speedup 1.0000x reference)
#include <cuda_runtime.h>
#include <math.h>

// Post_rois: SSD post-processing (softmax scores + box decode + greedy NMS + top-200)
// Inputs: loc [8,4096,4] f32, conf [8*4096,2] f32, prior [4096,4] f32 (cx,cy,w,h)
// Output: f32 [8, 2, 200, 5]; class-0 slice zeros, class-1 = NMS rows [s,x1,y1,x2,y2].

#define BATCH    8
#define NPRI     4096
#define TOPK     200
#define BLK      512      // 8 elements per thread
#define EPT      8
#define CONF_TH  0.01f
#define NMS_TH   0.45f

// dynamic smem: uint64 spk[4096] (32KB) + float4 sbox[4096] (64KB) + float sarea[4096] (16KB)
#define SMEM_BYTES (NPRI * (8 + 16 + 4))

typedef unsigned long long u64;

// compare-exchange: a is the LOWER-index element. desc=true -> a gets the max.
__device__ __forceinline__ void ce(u64 &a, u64 &b, bool desc) {
    u64 lo = a < b ? a : b;
    u64 hi = a < b ? b : a;
    a = desc ? hi : lo;
    b = desc ? lo : hi;
}

// full local merge of an 8-element bitonic sequence, uniform direction
__device__ __forceinline__ void local_merge8(u64 v[EPT], bool d) {
    ce(v[0],v[4],d); ce(v[1],v[5],d); ce(v[2],v[6],d); ce(v[3],v[7],d);
    ce(v[0],v[2],d); ce(v[1],v[3],d); ce(v[4],v[6],d); ce(v[5],v[7],d);
    ce(v[0],v[1],d); ce(v[2],v[3],d); ce(v[4],v[5],d); ce(v[6],v[7],d);
}

// phases k=2,4,8 within one thread's 8 contiguous elements (i = 8*tid + r)
__device__ __forceinline__ void local_sort8(u64 v[EPT], bool dir8) {
    // k=2 (dir = ((i&2)==0))
    ce(v[0],v[1],true);  ce(v[2],v[3],false); ce(v[4],v[5],true);  ce(v[6],v[7],false);
    // k=4, j=2 (dir = ((i&4)==0))
    ce(v[0],v[2],true);  ce(v[1],v[3],true);  ce(v[4],v[6],false); ce(v[5],v[7],false);
    // k=4, j=1
    ce(v[0],v[1],true);  ce(v[2],v[3],true);  ce(v[4],v[5],false); ce(v[6],v[7],false);
    // k=8 (dir uniform per thread)
    local_merge8(v, dir8);
}

// cross-thread (within-warp) stage j = 8*d via shfl.xor; dir uniform per warp here
__device__ __forceinline__ void shfl_stage(u64 v[EPT], int d, bool dirT, int tid) {
    bool keep_max = (((tid & d) == 0) == dirT);
    #pragma unroll
    for (int r = 0; r < EPT; r++) {
        u64 o = __shfl_xor_sync(0xffffffffu, v[r], d);
        v[r] = keep_max ? (v[r] > o ? v[r] : o) : (v[r] < o ? v[r] : o);
    }
}

__global__ __launch_bounds__(BLK, 1)
void post_rois_kernel(const float* __restrict__ loc,
                      const float* __restrict__ conf,
                      const float* __restrict__ prior,
                      float* __restrict__ out)
{
    const int b   = blockIdx.x;
    const int tid = threadIdx.x;

    extern __shared__ unsigned char smem_raw[];
    u64*    spk   = (u64*)smem_raw;                 // packed (score, idx), sorted desc
    float4* sbox  = (float4*)(spk + NPRI);          // decoded boxes in sorted order
    float*  sarea = (float*)(sbox + NPRI);

    // ---- zero this image's output slice ----
    float* ob = out + (size_t)b * 2 * TOPK * 5;
    for (int i = tid; i < 2 * TOPK * 5; i += BLK) ob[i] = 0.0f;

    // ---- phase 1: softmax scores, pack into sortable u64 ----
    // desc order on packed == (-score asc, idx asc) == reference stable argsort(-scores)
    for (int n = tid; n < NPRI; n += BLK) {
        float c0 = conf[((size_t)b * NPRI + n) * 2 + 0];
        float c1 = conf[((size_t)b * NPRI + n) * 2 + 1];
        float m  = fmaxf(c0, c1);
        float e0 = expf(__fsub_rn(c0, m));
        float e1 = expf(__fsub_rn(c1, m));
        float s  = __fdiv_rn(e1, __fadd_rn(e0, e1));   // in (0,1): positive, bits monotone
        spk[n] = ((u64)__float_as_uint(s) << 32) | (unsigned)(NPRI - 1 - n);
    }
    __syncthreads();

    // ---- phase 2: bitonic sort (descending), 8 elems/thread in registers ----
    u64 v[EPT];
    #pragma unroll
    for (int r = 0; r < EPT; r++) v[r] = spk[tid * EPT + r];

    local_sort8(v, (tid & 1) == 0);                       // k = 2,4,8

    for (int k = 16; k <= 256; k <<= 1) {                 // fully warp-local, 0 barriers
        bool dirT = ((tid & (k >> 3)) == 0);
        for (int d = (k >> 4); d >= 1; d >>= 1) shfl_stage(v, d, dirT, tid);
        local_merge8(v, dirT);
    }

    for (int k = 512; k <= (int)NPRI; k <<= 1) {          // cross-warp phases
        #pragma unroll
        for (int r = 0; r < EPT; r++) spk[tid * EPT + r] = v[r];
        __syncthreads();
        for (int j = (k >> 1); j >= 256; j >>= 1) {       // smem stages
            for (int m = tid; m < NPRI / 2; m += BLK) {
                int i = ((m & ~(j - 1)) << 1) | (m & (j - 1));
                int p = i | j;
                u64 a = spk[i], c = spk[p];
                bool desc = ((i & k) == 0);
                if (desc ? (a < c) : (a > c)) { spk[i] = c; spk[p] = a; }
            }
            __syncthreads();
        }
        #pragma unroll
        for (int r = 0; r < EPT; r++) v[r] = spk[tid * EPT + r];
        bool dirT = ((tid & (k >> 3)) == 0);
        for (int d = 16; d >= 1; d >>= 1) shfl_stage(v, d, dirT, tid);
        local_merge8(v, dirT);
    }

    #pragma unroll
    for (int r = 0; r < EPT; r++) spk[tid * EPT + r] = v[r];
    __syncthreads();

    // ---- phase 3: decode boxes into sorted order (pinned IEEE, no FMA) ----
    for (int p = tid; p < NPRI; p += BLK) {
        int n = NPRI - 1 - (int)(unsigned)(spk[p] & 0xffffffffu);
        const float* lp = loc + ((size_t)b * NPRI + n) * 4;
        float lx = lp[0], ly = lp[1], lw = lp[2], lh = lp[3];
        float pcx = prior[n * 4 + 0], pcy = prior[n * 4 + 1];
        float pw  = prior[n * 4 + 2], ph  = prior[n * 4 + 3];

        float cx = __fadd_rn(pcx, __fmul_rn(__fmul_rn(lx, 0.1f), pw));
        float cy = __fadd_rn(pcy, __fmul_rn(__fmul_rn(ly, 0.1f), ph));
        float w  = __fmul_rn(pw, expf(__fmul_rn(lw, 0.2f)));
        float h  = __fmul_rn(ph, expf(__fmul_rn(lh, 0.2f)));
        float hw = __fmul_rn(w, 0.5f);
        float hh = __fmul_rn(h, 0.5f);
        float x1 = __fsub_rn(cx, hw), y1 = __fsub_rn(cy, hh);
        float x2 = __fadd_rn(cx, hw), y2 = __fadd_rn(cy, hh);

        sbox[p]  = make_float4(x1, y1, x2, y2);
        sarea[p] = __fmul_rn(__fsub_rn(x2, x1), __fsub_rn(y2, y1));
    }
    __syncthreads();

    // ---- phase 4: greedy NMS, single warp, kept set in registers ----
    // kept box k lives at lane (k & 31), register slot (k >> 5); kept < 200 -> <= 7 slots
    if (tid < 32) {
        float4 kb[7];
        float  ka[7];
        int kept = 0;

        for (int i = 0; i < NPRI && kept < TOPK; i++) {
            u64 pk  = spk[i];                                   // smem broadcast
            float s = __uint_as_float((unsigned)(pk >> 32));
            if (!(s > CONF_TH)) break;                          // sorted desc

            float4 bi = sbox[i];
            float  ai = sarea[i];

            bool sup = false;
            #pragma unroll
            for (int r = 0; r < 7; r++) {
                if ((r << 5) + tid < kept) {
                    float iw = fmaxf(__fsub_rn(fminf(bi.z, kb[r].z), fmaxf(bi.x, kb[r].x)), 0.0f);
                    float ih = fmaxf(__fsub_rn(fminf(bi.w, kb[r].w), fmaxf(bi.y, kb[r].y)), 0.0f);
                    float inter = __fmul_rn(iw, ih);
                    float denom = __fsub_rn(__fadd_rn(ka[r], ai), inter);
                    sup |= (__fdiv_rn(inter, denom) > NMS_TH);
                }
            }
            if (__any_sync(0xffffffffu, sup)) continue;

            #pragma unroll
            for (int r = 0; r < 7; r++) {
                if ((kept >> 5) == r && (kept & 31) == tid) { kb[r] = bi; ka[r] = ai; }
            }
            if (tid == 0) {
                float* row = ob + (size_t)(TOPK + kept) * 5;    // class-1 slice
                row[0] = s;
                row[1] = bi.x; row[2] = bi.y; row[3] = bi.z; row[4] = bi.w;
            }
            kept++;
        }
    }
}

extern "C" void kernel_launch(void* const* d_in, const int* in_sizes, int n_in,
                              void* d_out, int out_size)
{
    const float* loc   = (const float*)d_in[0];
    const float* conf  = (const float*)d_in[1];
    const float* prior = (const float*)d_in[2];
    float* out = (float*)d_out;

    cudaFuncSetAttribute(post_rois_kernel,
                         cudaFuncAttributeMaxDynamicSharedMemorySize, SMEM_BYTES);
    post_rois_kernel<<<BATCH, BLK, SMEM_BYTES>>>(loc, conf, prior, out);
}